// round 3
// baseline (speedup 1.0000x reference)
#include <cuda_runtime.h>
#include <math.h>

#define BB 4
#define TT 1024
#define DMODEL 512
#define HH 8
#define NEG_INF_F (-1000000000.0f)

// ---------------- scratch (device globals; no allocation) ----------------
__device__ float g_q[BB*TT*DMODEL];
__device__ float g_k[BB*TT*DMODEL];
__device__ float g_v[BB*TT*DMODEL];
__device__ float g_ctx[BB*TT*DMODEL];
__device__ float g_res[BB*TT*DMODEL];
__device__ float g_scores[(size_t)HH*BB*TT*TT];   // 134 MB
__device__ float g_maskv[HH*DMODEL];
__device__ float g_m2[HH*DMODEL];
__device__ float g_inv_scale[HH];
__device__ int   g_dlo[HH];
__device__ int   g_dhi[HH];

// ---------------- block reductions ----------------
__device__ __forceinline__ float block_reduce_sum(float v) {
    __shared__ float sh[32];
    __syncthreads();
    int lane = threadIdx.x & 31, wid = threadIdx.x >> 5;
    #pragma unroll
    for (int o = 16; o > 0; o >>= 1) v += __shfl_xor_sync(0xffffffffu, v, o);
    if (lane == 0) sh[wid] = v;
    __syncthreads();
    if (wid == 0) {
        int nw = blockDim.x >> 5;
        v = (lane < nw) ? sh[lane] : 0.0f;
        #pragma unroll
        for (int o = 16; o > 0; o >>= 1) v += __shfl_xor_sync(0xffffffffu, v, o);
        if (lane == 0) sh[0] = v;
    }
    __syncthreads();
    return sh[0];
}

__device__ __forceinline__ float block_reduce_max(float v) {
    __shared__ float sh[32];
    __syncthreads();
    int lane = threadIdx.x & 31, wid = threadIdx.x >> 5;
    #pragma unroll
    for (int o = 16; o > 0; o >>= 1) v = fmaxf(v, __shfl_xor_sync(0xffffffffu, v, o));
    if (lane == 0) sh[wid] = v;
    __syncthreads();
    if (wid == 0) {
        int nw = blockDim.x >> 5;
        v = (lane < nw) ? sh[lane] : -INFINITY;
        #pragma unroll
        for (int o = 16; o > 0; o >>= 1) v = fmaxf(v, __shfl_xor_sync(0xffffffffu, v, o));
        if (lane == 0) sh[0] = v;
    }
    __syncthreads();
    return sh[0];
}

// ---------------- K1: head params / masks / windows ----------------
__global__ void head_params_kernel(const float* __restrict__ hw) {
    __shared__ float dims[HH], starts[HH];
    int tid = threadIdx.x;
    if (tid == 0) {
        float mx = -1e30f;
        for (int h = 0; h < HH; h++) mx = fmaxf(mx, hw[h]);
        float e[HH]; float s = 0.0f;
        for (int h = 0; h < HH; h++) { e[h] = expf(hw[h] - mx); s += e[h]; }
        float run = 0.0f;
        const float adj = (float)(DMODEL - 16*HH);   // 384
        for (int h = 0; h < HH; h++) {
            float gg = e[h] / s;
            float dd = fmaxf(16.0f + gg * adj, 0.0f);
            dims[h] = dd; starts[h] = run;
            g_inv_scale[h] = rsqrtf(dd + 1e-6f);
            int lo = (int)floorf(run - 2.5f);        if (lo < 0) lo = 0;
            int hi = (int)ceilf(run + dd + 2.5f);    if (hi > DMODEL) hi = DMODEL;
            g_dlo[h] = lo; g_dhi[h] = hi;
            run += dd;
        }
    }
    __syncthreads();
    float p = (float)tid;   // tid in [0,512)
    for (int h = 0; h < HH; h++) {
        float l = 1.0f / (1.0f + expf(-(p - starts[h]) * 10.0f));
        float r = 1.0f / (1.0f + expf(-(starts[h] + dims[h] - p) * 10.0f));
        float m = l * r;
        g_maskv[h*DMODEL + tid] = m;
        g_m2[h*DMODEL + tid]   = m * m;
    }
}

// ---------------- K2: QKV projection GEMM (4096x1536x512) ----------------
__global__ __launch_bounds__(256) void sgemm_qkv(const float* __restrict__ A,
                                                 const float* __restrict__ B,
                                                 const float* __restrict__ bias) {
    const int K = DMODEL, N = 3*DMODEL;
    __shared__ float As[8][128];
    __shared__ float Bs[8][128];
    int tid = threadIdx.x;
    int tx = tid & 15, ty = tid >> 4;
    int aRow = tid >> 1, aCol = (tid & 1) << 2;
    int bRow = tid >> 5, bCol = (tid & 31) << 2;
    const float* Ablk = A + (size_t)(blockIdx.y * 128) * K;
    const float* Bblk = B + blockIdx.x * 128;
    float acc[8][8] = {};
    for (int k0 = 0; k0 < K; k0 += 8) {
        float4 av = *(const float4*)(Ablk + (size_t)aRow * K + k0 + aCol);
        As[aCol+0][aRow] = av.x; As[aCol+1][aRow] = av.y;
        As[aCol+2][aRow] = av.z; As[aCol+3][aRow] = av.w;
        *(float4*)&Bs[bRow][bCol] = *(const float4*)(Bblk + (size_t)(k0 + bRow) * N + bCol);
        __syncthreads();
        #pragma unroll
        for (int kk = 0; kk < 8; kk++) {
            float4 a0 = *(const float4*)&As[kk][ty*8];
            float4 a1 = *(const float4*)&As[kk][ty*8+4];
            float4 b0 = *(const float4*)&Bs[kk][tx*8];
            float4 b1 = *(const float4*)&Bs[kk][tx*8+4];
            float ar[8] = {a0.x,a0.y,a0.z,a0.w,a1.x,a1.y,a1.z,a1.w};
            float br[8] = {b0.x,b0.y,b0.z,b0.w,b1.x,b1.y,b1.z,b1.w};
            #pragma unroll
            for (int i = 0; i < 8; i++)
                #pragma unroll
                for (int j = 0; j < 8; j++) acc[i][j] += ar[i]*br[j];
        }
        __syncthreads();
    }
    int row0 = blockIdx.y*128 + ty*8;
    int col0 = blockIdx.x*128 + tx*8;
    #pragma unroll
    for (int i = 0; i < 8; i++) {
        int row = row0 + i;
        #pragma unroll
        for (int j = 0; j < 8; j++) {
            int col = col0 + j;
            float v = acc[i][j] + bias[col];
            if (col < DMODEL)            g_q[(size_t)row*DMODEL + col]            = v;
            else if (col < 2*DMODEL)     g_k[(size_t)row*DMODEL + col - DMODEL]   = v;
            else                         g_v[(size_t)row*DMODEL + col - 2*DMODEL] = v;
        }
    }
}

// ---------------- K3: scores = (q*m2) @ k^T * inv_scale (windowed) ----------------
__global__ __launch_bounds__(256) void scores_kernel(const unsigned char* __restrict__ kpm) {
    int z = blockIdx.z; int h = z >> 2; int b = z & 3;
    int lo = g_dlo[h] & ~7;
    int hi = (g_dhi[h] + 7) & ~7;
    const float* Q  = g_q + (size_t)b*TT*DMODEL;
    const float* Kp = g_k + (size_t)b*TT*DMODEL;
    const float* m2 = g_m2 + h*DMODEL;
    __shared__ float As[8][128];
    __shared__ float Bs[8][128];
    int tid = threadIdx.x;
    int tx = tid & 15, ty = tid >> 4;
    int aRow = tid >> 1, aCol = (tid & 1) << 2;
    int t0 = blockIdx.y * 128;
    int s0 = blockIdx.x * 128;
    float acc[8][8] = {};
    for (int k0 = lo; k0 < hi; k0 += 8) {
        float4 qv = *(const float4*)(Q  + (size_t)(t0 + aRow)*DMODEL + k0 + aCol);
        float4 mv = *(const float4*)(m2 + k0 + aCol);
        As[aCol+0][aRow] = qv.x*mv.x; As[aCol+1][aRow] = qv.y*mv.y;
        As[aCol+2][aRow] = qv.z*mv.z; As[aCol+3][aRow] = qv.w*mv.w;
        float4 kv = *(const float4*)(Kp + (size_t)(s0 + aRow)*DMODEL + k0 + aCol);
        Bs[aCol+0][aRow] = kv.x; Bs[aCol+1][aRow] = kv.y;
        Bs[aCol+2][aRow] = kv.z; Bs[aCol+3][aRow] = kv.w;
        __syncthreads();
        #pragma unroll
        for (int kk = 0; kk < 8; kk++) {
            float4 a0 = *(const float4*)&As[kk][ty*8];
            float4 a1 = *(const float4*)&As[kk][ty*8+4];
            float4 b0 = *(const float4*)&Bs[kk][tx*8];
            float4 b1 = *(const float4*)&Bs[kk][tx*8+4];
            float ar[8] = {a0.x,a0.y,a0.z,a0.w,a1.x,a1.y,a1.z,a1.w};
            float br[8] = {b0.x,b0.y,b0.z,b0.w,b1.x,b1.y,b1.z,b1.w};
            #pragma unroll
            for (int i = 0; i < 8; i++)
                #pragma unroll
                for (int j = 0; j < 8; j++) acc[i][j] += ar[i]*br[j];
        }
        __syncthreads();
    }
    float isc = g_inv_scale[h];
    float* Sout = g_scores + (size_t)z*TT*TT;
    #pragma unroll
    for (int i = 0; i < 8; i++) {
        int t = t0 + ty*8 + i;
        #pragma unroll
        for (int j = 0; j < 8; j++) {
            int s = s0 + tx*8 + j;
            float v = acc[i][j] * isc;
            if (kpm[b*TT + s]) v = NEG_INF_F;
            Sout[(size_t)t*TT + s] = v;
        }
    }
}

// ---------------- K4: row softmax over scores (in place) ----------------
__global__ __launch_bounds__(256) void softmax_kernel() {
    size_t row = blockIdx.x;
    float4* S = (float4*)(g_scores + row * TT);
    int tid = threadIdx.x;
    float4 v = S[tid];
    float m = fmaxf(fmaxf(v.x, v.y), fmaxf(v.z, v.w));
    m = block_reduce_max(m);
    float e0 = expf(v.x - m), e1 = expf(v.y - m);
    float e2 = expf(v.z - m), e3 = expf(v.w - m);
    float s = block_reduce_sum(e0 + e1 + e2 + e3);
    float inv = 1.0f / s;
    S[tid] = make_float4(e0*inv, e1*inv, e2*inv, e3*inv);
}

// ---------------- K5a: zero ctx ----------------
__global__ void zero_ctx_kernel() {
    int i = blockIdx.x * blockDim.x + threadIdx.x;
    ((float4*)g_ctx)[i] = make_float4(0.f, 0.f, 0.f, 0.f);
}

// ---------------- K5: ctx += P @ (v * mask)  (windowed, atomic accumulate) ----------------
__global__ __launch_bounds__(256) void ctx_kernel() {
    int z = blockIdx.z; int h = z >> 2; int b = z & 3;
    int d0 = blockIdx.x * 64;
    if (d0 >= g_dhi[h] || d0 + 64 <= g_dlo[h]) return;
    const float* P   = g_scores + (size_t)z*TT*TT;
    const float* V   = g_v + (size_t)b*TT*DMODEL;
    const float* msk = g_maskv + h*DMODEL;
    __shared__ float As[8][128];
    __shared__ float Bs[8][64];
    int tid = threadIdx.x;
    int tx = tid & 15, ty = tid >> 4;         // thread tile 8 rows x 4 cols
    int aRow = tid >> 1, aCol = (tid & 1) << 2;
    int bRow = tid >> 5, bCol = (tid & 31) << 1;
    int t0 = blockIdx.y * 128;
    float acc[8][4] = {};
    for (int s0 = 0; s0 < TT; s0 += 8) {
        float4 pv = *(const float4*)(P + (size_t)(t0 + aRow)*TT + s0 + aCol);
        As[aCol+0][aRow] = pv.x; As[aCol+1][aRow] = pv.y;
        As[aCol+2][aRow] = pv.z; As[aCol+3][aRow] = pv.w;
        float2 vv = *(const float2*)(V + (size_t)(s0 + bRow)*DMODEL + d0 + bCol);
        Bs[bRow][bCol]   = vv.x;
        Bs[bRow][bCol+1] = vv.y;
        __syncthreads();
        #pragma unroll
        for (int kk = 0; kk < 8; kk++) {
            float4 a0 = *(const float4*)&As[kk][ty*8];
            float4 a1 = *(const float4*)&As[kk][ty*8+4];
            float4 b0 = *(const float4*)&Bs[kk][tx*4];
            float ar[8] = {a0.x,a0.y,a0.z,a0.w,a1.x,a1.y,a1.z,a1.w};
            float br[4] = {b0.x,b0.y,b0.z,b0.w};
            #pragma unroll
            for (int i = 0; i < 8; i++)
                #pragma unroll
                for (int j = 0; j < 4; j++) acc[i][j] += ar[i]*br[j];
        }
        __syncthreads();
    }
    float mk[4];
    #pragma unroll
    for (int j = 0; j < 4; j++) mk[j] = msk[d0 + tx*4 + j];
    #pragma unroll
    for (int i = 0; i < 8; i++) {
        int t = t0 + ty*8 + i;
        #pragma unroll
        for (int j = 0; j < 4; j++) {
            int d = d0 + tx*4 + j;
            atomicAdd(&g_ctx[(size_t)b*TT*DMODEL + (size_t)t*DMODEL + d], acc[i][j] * mk[j]);
        }
    }
}

// ---------------- K6: out = ctx @ Wout + bout + query -> g_res ----------------
__global__ __launch_bounds__(256) void sgemm_out(const float* __restrict__ B,
                                                 const float* __restrict__ bias,
                                                 const float* __restrict__ resid) {
    const int K = DMODEL, N = DMODEL;
    __shared__ float As[8][128];
    __shared__ float Bs[8][128];
    int tid = threadIdx.x;
    int tx = tid & 15, ty = tid >> 4;
    int aRow = tid >> 1, aCol = (tid & 1) << 2;
    int bRow = tid >> 5, bCol = (tid & 31) << 2;
    const float* Ablk = g_ctx + (size_t)(blockIdx.y * 128) * K;
    const float* Bblk = B + blockIdx.x * 128;
    float acc[8][8] = {};
    for (int k0 = 0; k0 < K; k0 += 8) {
        float4 av = *(const float4*)(Ablk + (size_t)aRow * K + k0 + aCol);
        As[aCol+0][aRow] = av.x; As[aCol+1][aRow] = av.y;
        As[aCol+2][aRow] = av.z; As[aCol+3][aRow] = av.w;
        *(float4*)&Bs[bRow][bCol] = *(const float4*)(Bblk + (size_t)(k0 + bRow) * N + bCol);
        __syncthreads();
        #pragma unroll
        for (int kk = 0; kk < 8; kk++) {
            float4 a0 = *(const float4*)&As[kk][ty*8];
            float4 a1 = *(const float4*)&As[kk][ty*8+4];
            float4 b0 = *(const float4*)&Bs[kk][tx*8];
            float4 b1 = *(const float4*)&Bs[kk][tx*8+4];
            float ar[8] = {a0.x,a0.y,a0.z,a0.w,a1.x,a1.y,a1.z,a1.w};
            float br[8] = {b0.x,b0.y,b0.z,b0.w,b1.x,b1.y,b1.z,b1.w};
            #pragma unroll
            for (int i = 0; i < 8; i++)
                #pragma unroll
                for (int j = 0; j < 8; j++) acc[i][j] += ar[i]*br[j];
        }
        __syncthreads();
    }
    int row0 = blockIdx.y*128 + ty*8;
    int col0 = blockIdx.x*128 + tx*8;
    #pragma unroll
    for (int i = 0; i < 8; i++) {
        int row = row0 + i;
        #pragma unroll
        for (int j = 0; j < 8; j++) {
            int col = col0 + j;
            g_res[(size_t)row*DMODEL + col] =
                acc[i][j] + bias[col] + resid[(size_t)row*DMODEL + col];
        }
    }
}

// ---------------- K7: LayerNorm -> d_out ----------------
__global__ __launch_bounds__(256) void ln_kernel(const float* __restrict__ gamma,
                                                 const float* __restrict__ beta,
                                                 float* __restrict__ out) {
    int row = blockIdx.x;
    int tid = threadIdx.x;
    float2 v = ((const float2*)(g_res + (size_t)row*DMODEL))[tid];
    float s = block_reduce_sum(v.x + v.y);
    float mu = s * (1.0f / DMODEL);
    float d0 = v.x - mu, d1 = v.y - mu;
    float sq = block_reduce_sum(d0*d0 + d1*d1);
    float var = sq * (1.0f / DMODEL);
    float r = rsqrtf(var + 1e-5f);
    float2 g  = ((const float2*)gamma)[tid];
    float2 bt = ((const float2*)beta)[tid];
    float2 o;
    o.x = d0 * r * g.x + bt.x;
    o.y = d1 * r * g.y + bt.y;
    ((float2*)(out + (size_t)row*DMODEL))[tid] = o;
}

// ---------------- launch ----------------
extern "C" void kernel_launch(void* const* d_in, const int* in_sizes, int n_in,
                              void* d_out, int out_size) {
    const float* query = (const float*)d_in[0];
    const float* hw    = (const float*)d_in[1];
    const float* Wqkv  = (const float*)d_in[2];
    const float* bqkv  = (const float*)d_in[3];
    const float* Wout  = (const float*)d_in[4];
    const float* bout  = (const float*)d_in[5];
    const float* gamma = (const float*)d_in[6];
    const float* beta  = (const float*)d_in[7];
    const unsigned char* kpm = (const unsigned char*)d_in[8];
    float* out = (float*)d_out;

    head_params_kernel<<<1, DMODEL>>>(hw);
    sgemm_qkv<<<dim3(3*DMODEL/128, BB*TT/128), 256>>>(query, Wqkv, bqkv);
    zero_ctx_kernel<<<(BB*TT*DMODEL/4)/256, 256>>>();
    scores_kernel<<<dim3(TT/128, TT/128, HH*BB), 256>>>(kpm);
    softmax_kernel<<<HH*BB*TT, 256>>>();
    ctx_kernel<<<dim3(DMODEL/64, TT/128, HH*BB), 256>>>();
    sgemm_out<<<dim3(DMODEL/128, BB*TT/128), 256>>>(Wout, bout, query);
    ln_kernel<<<BB*TT, 256>>>(gamma, beta, out);
}

// round 4
// speedup vs baseline: 1.1263x; 1.1263x over previous
#include <cuda_runtime.h>
#include <math.h>

#define BB 4
#define TT 1024
#define DMODEL 512
#define HH 8
#define NEG_INF_F (-1000000000.0f)
#define NROWS (HH*BB*TT)   // 32768 softmax rows

// ---------------- scratch (device globals; no allocation) ----------------
__device__ float g_q[BB*TT*DMODEL];
__device__ float g_k[BB*TT*DMODEL];
__device__ float g_v[BB*TT*DMODEL];
__device__ float g_ctx[BB*TT*DMODEL];
__device__ float g_res[BB*TT*DMODEL];
__device__ float g_scores[(size_t)HH*BB*TT*TT];   // 134 MB
__device__ float g_smax[NROWS*8];                 // per (row, s-tile) max
__device__ float g_ssum[NROWS*8];                 // per (row, s-tile) sumexp
__device__ float g_mrow[NROWS];                   // combined row max
__device__ float g_linv[NROWS];                   // combined 1/sumexp
__device__ float g_maskv[HH*DMODEL];
__device__ float g_m2[HH*DMODEL];
__device__ float g_inv_scale[HH];
__device__ int   g_dlo[HH];
__device__ int   g_dhi[HH];

// ---------------- block reductions (for LN) ----------------
__device__ __forceinline__ float block_reduce_sum(float v) {
    __shared__ float sh[32];
    __syncthreads();
    int lane = threadIdx.x & 31, wid = threadIdx.x >> 5;
    #pragma unroll
    for (int o = 16; o > 0; o >>= 1) v += __shfl_xor_sync(0xffffffffu, v, o);
    if (lane == 0) sh[wid] = v;
    __syncthreads();
    if (wid == 0) {
        int nw = blockDim.x >> 5;
        v = (lane < nw) ? sh[lane] : 0.0f;
        #pragma unroll
        for (int o = 16; o > 0; o >>= 1) v += __shfl_xor_sync(0xffffffffu, v, o);
        if (lane == 0) sh[0] = v;
    }
    __syncthreads();
    return sh[0];
}

// ---------------- K1: head params / masks / windows ----------------
__global__ void head_params_kernel(const float* __restrict__ hw) {
    __shared__ float dims[HH], starts[HH];
    int tid = threadIdx.x;
    if (tid == 0) {
        float mx = -1e30f;
        for (int h = 0; h < HH; h++) mx = fmaxf(mx, hw[h]);
        float e[HH]; float s = 0.0f;
        for (int h = 0; h < HH; h++) { e[h] = expf(hw[h] - mx); s += e[h]; }
        float run = 0.0f;
        const float adj = (float)(DMODEL - 16*HH);   // 384
        for (int h = 0; h < HH; h++) {
            float gg = e[h] / s;
            float dd = fmaxf(16.0f + gg * adj, 0.0f);
            dims[h] = dd; starts[h] = run;
            g_inv_scale[h] = rsqrtf(dd + 1e-6f);
            int lo = (int)floorf(run - 2.5f);        if (lo < 0) lo = 0;
            int hi = (int)ceilf(run + dd + 2.5f);    if (hi > DMODEL) hi = DMODEL;
            g_dlo[h] = lo; g_dhi[h] = hi;
            run += dd;
        }
    }
    __syncthreads();
    float p = (float)tid;   // tid in [0,512)
    for (int h = 0; h < HH; h++) {
        float l = 1.0f / (1.0f + expf(-(p - starts[h]) * 10.0f));
        float r = 1.0f / (1.0f + expf(-(starts[h] + dims[h] - p) * 10.0f));
        float m = l * r;
        g_maskv[h*DMODEL + tid] = m;
        g_m2[h*DMODEL + tid]   = m * m;
    }
}

// ---------------- K2: QKV projection GEMM (4096x1536x512), KTILE=16 ----------------
__global__ __launch_bounds__(256) void sgemm_qkv(const float* __restrict__ A,
                                                 const float* __restrict__ B,
                                                 const float* __restrict__ bias) {
    const int K = DMODEL, N = 3*DMODEL;
    __shared__ float As[16][128];
    __shared__ float Bs[16][128];
    int tid = threadIdx.x;
    int tx = tid & 15, ty = tid >> 4;
    int aRow = tid >> 1, aColB = (tid & 1) << 3;
    int bRow = tid >> 4, bColB = (tid & 15) << 3;
    const float* Ablk = A + (size_t)(blockIdx.y * 128) * K;
    const float* Bblk = B + blockIdx.x * 128;
    float acc[8][8] = {};
    for (int k0 = 0; k0 < K; k0 += 16) {
        float4 a0v = *(const float4*)(Ablk + (size_t)aRow * K + k0 + aColB);
        float4 a1v = *(const float4*)(Ablk + (size_t)aRow * K + k0 + aColB + 4);
        As[aColB+0][aRow] = a0v.x; As[aColB+1][aRow] = a0v.y;
        As[aColB+2][aRow] = a0v.z; As[aColB+3][aRow] = a0v.w;
        As[aColB+4][aRow] = a1v.x; As[aColB+5][aRow] = a1v.y;
        As[aColB+6][aRow] = a1v.z; As[aColB+7][aRow] = a1v.w;
        *(float4*)&Bs[bRow][bColB]   = *(const float4*)(Bblk + (size_t)(k0 + bRow) * N + bColB);
        *(float4*)&Bs[bRow][bColB+4] = *(const float4*)(Bblk + (size_t)(k0 + bRow) * N + bColB + 4);
        __syncthreads();
        #pragma unroll
        for (int kk = 0; kk < 16; kk++) {
            float4 a0 = *(const float4*)&As[kk][ty*8];
            float4 a1 = *(const float4*)&As[kk][ty*8+4];
            float4 b0 = *(const float4*)&Bs[kk][tx*8];
            float4 b1 = *(const float4*)&Bs[kk][tx*8+4];
            float ar[8] = {a0.x,a0.y,a0.z,a0.w,a1.x,a1.y,a1.z,a1.w};
            float br[8] = {b0.x,b0.y,b0.z,b0.w,b1.x,b1.y,b1.z,b1.w};
            #pragma unroll
            for (int i = 0; i < 8; i++)
                #pragma unroll
                for (int j = 0; j < 8; j++) acc[i][j] += ar[i]*br[j];
        }
        __syncthreads();
    }
    int row0 = blockIdx.y*128 + ty*8;
    int col0 = blockIdx.x*128 + tx*8;
    #pragma unroll
    for (int i = 0; i < 8; i++) {
        int row = row0 + i;
        #pragma unroll
        for (int j = 0; j < 8; j++) {
            int col = col0 + j;
            float v = acc[i][j] + bias[col];
            if (col < DMODEL)            g_q[(size_t)row*DMODEL + col]            = v;
            else if (col < 2*DMODEL)     g_k[(size_t)row*DMODEL + col - DMODEL]   = v;
            else                         g_v[(size_t)row*DMODEL + col - 2*DMODEL] = v;
        }
    }
}

// ---------------- K3: scores + per-tile softmax stats (windowed, KTILE=16) ----------------
__global__ __launch_bounds__(256) void scores_kernel(const unsigned char* __restrict__ kpm) {
    int z = blockIdx.z; int h = z >> 2; int b = z & 3;
    int lo = g_dlo[h] & ~15;
    int hi = (g_dhi[h] + 15) & ~15;
    const float* Q  = g_q + (size_t)b*TT*DMODEL;
    const float* Kp = g_k + (size_t)b*TT*DMODEL;
    const float* m2 = g_m2 + h*DMODEL;
    __shared__ float As[16][128];
    __shared__ float Bs[16][128];
    int tid = threadIdx.x;
    int tx = tid & 15, ty = tid >> 4;
    int aRow = tid >> 1, aColB = (tid & 1) << 3;
    int t0 = blockIdx.y * 128;
    int s0 = blockIdx.x * 128;
    float acc[8][8] = {};
    for (int k0 = lo; k0 < hi; k0 += 16) {
        float4 q0 = *(const float4*)(Q  + (size_t)(t0 + aRow)*DMODEL + k0 + aColB);
        float4 q1 = *(const float4*)(Q  + (size_t)(t0 + aRow)*DMODEL + k0 + aColB + 4);
        float4 m0 = *(const float4*)(m2 + k0 + aColB);
        float4 m1 = *(const float4*)(m2 + k0 + aColB + 4);
        As[aColB+0][aRow] = q0.x*m0.x; As[aColB+1][aRow] = q0.y*m0.y;
        As[aColB+2][aRow] = q0.z*m0.z; As[aColB+3][aRow] = q0.w*m0.w;
        As[aColB+4][aRow] = q1.x*m1.x; As[aColB+5][aRow] = q1.y*m1.y;
        As[aColB+6][aRow] = q1.z*m1.z; As[aColB+7][aRow] = q1.w*m1.w;
        float4 k0v = *(const float4*)(Kp + (size_t)(s0 + aRow)*DMODEL + k0 + aColB);
        float4 k1v = *(const float4*)(Kp + (size_t)(s0 + aRow)*DMODEL + k0 + aColB + 4);
        Bs[aColB+0][aRow] = k0v.x; Bs[aColB+1][aRow] = k0v.y;
        Bs[aColB+2][aRow] = k0v.z; Bs[aColB+3][aRow] = k0v.w;
        Bs[aColB+4][aRow] = k1v.x; Bs[aColB+5][aRow] = k1v.y;
        Bs[aColB+6][aRow] = k1v.z; Bs[aColB+7][aRow] = k1v.w;
        __syncthreads();
        #pragma unroll
        for (int kk = 0; kk < 16; kk++) {
            float4 a0 = *(const float4*)&As[kk][ty*8];
            float4 a1 = *(const float4*)&As[kk][ty*8+4];
            float4 b0 = *(const float4*)&Bs[kk][tx*8];
            float4 b1 = *(const float4*)&Bs[kk][tx*8+4];
            float ar[8] = {a0.x,a0.y,a0.z,a0.w,a1.x,a1.y,a1.z,a1.w};
            float br[8] = {b0.x,b0.y,b0.z,b0.w,b1.x,b1.y,b1.z,b1.w};
            #pragma unroll
            for (int i = 0; i < 8; i++)
                #pragma unroll
                for (int j = 0; j < 8; j++) acc[i][j] += ar[i]*br[j];
        }
        __syncthreads();
    }
    float isc = g_inv_scale[h];
    // padding mask for this thread's 8 columns (same for all rows)
    float km[8];
    #pragma unroll
    for (int j = 0; j < 8; j++) km[j] = kpm[b*TT + s0 + tx*8 + j] ? 1.0f : 0.0f;

    float* Sout = g_scores + (size_t)z*TT*TT;
    int stile = blockIdx.x;
    #pragma unroll
    for (int i = 0; i < 8; i++) {
        int t = t0 + ty*8 + i;
        float v[8];
        float mrow = -INFINITY;
        #pragma unroll
        for (int j = 0; j < 8; j++) {
            float x = acc[i][j] * isc;
            x = (km[j] != 0.0f) ? NEG_INF_F : x;
            v[j] = x;
            mrow = fmaxf(mrow, x);
        }
        // reduce max across the 16 tx lanes (contiguous lanes within half-warp)
        #pragma unroll
        for (int o = 8; o > 0; o >>= 1) mrow = fmaxf(mrow, __shfl_xor_sync(0xffffffffu, mrow, o));
        float lrow = 0.0f;
        #pragma unroll
        for (int j = 0; j < 8; j++) lrow += __expf(v[j] - mrow);
        #pragma unroll
        for (int o = 8; o > 0; o >>= 1) lrow += __shfl_xor_sync(0xffffffffu, lrow, o);
        if (tx == 0) {
            size_t ridx = ((size_t)z*TT + t)*8 + stile;
            g_smax[ridx] = mrow;
            g_ssum[ridx] = lrow;
        }
        float4 w0 = make_float4(v[0], v[1], v[2], v[3]);
        float4 w1 = make_float4(v[4], v[5], v[6], v[7]);
        *(float4*)&Sout[(size_t)t*TT + s0 + tx*8]     = w0;
        *(float4*)&Sout[(size_t)t*TT + s0 + tx*8 + 4] = w1;
    }
}

// ---------------- K4: combine per-tile stats -> (m, 1/l) per row ----------------
__global__ __launch_bounds__(256) void combine_kernel() {
    int r = blockIdx.x * 256 + threadIdx.x;
    if (r >= NROWS) return;
    float m[8], l[8];
    #pragma unroll
    for (int k = 0; k < 8; k++) { m[k] = g_smax[(size_t)r*8 + k]; l[k] = g_ssum[(size_t)r*8 + k]; }
    float mm = m[0];
    #pragma unroll
    for (int k = 1; k < 8; k++) mm = fmaxf(mm, m[k]);
    float ll = 0.0f;
    #pragma unroll
    for (int k = 0; k < 8; k++) ll += l[k] * __expf(m[k] - mm);
    g_mrow[r] = mm;
    g_linv[r] = 1.0f / ll;
}

// ---------------- K5a: zero ctx ----------------
__global__ void zero_ctx_kernel() {
    int i = blockIdx.x * blockDim.x + threadIdx.x;
    ((float4*)g_ctx)[i] = make_float4(0.f, 0.f, 0.f, 0.f);
}

// ---------------- K5: ctx += softmax(S) @ (v*mask), 128-wide d-chunk, KTILE=16 ----------------
__global__ __launch_bounds__(256) void ctx_kernel() {
    int z = blockIdx.z; int h = z >> 2; int b = z & 3;
    int dlo = g_dlo[h], dhi = g_dhi[h];
    int d0 = blockIdx.x * 128;
    if (d0 >= dhi || d0 + 128 <= dlo) return;
    const float* S   = g_scores + (size_t)z*TT*TT;
    const float* V   = g_v + (size_t)b*TT*DMODEL;
    const float* msk = g_maskv + h*DMODEL;
    __shared__ float As[16][128];   // P[s][t]
    __shared__ float Bs[16][128];   // V[s][d]
    int tid = threadIdx.x;
    int tx = tid & 15, ty = tid >> 4;
    int aRow = tid >> 1, aColB = (tid & 1) << 3;   // t index, s offset
    int bRow = tid >> 4, bColB = (tid & 15) << 3;  // s index, d offset
    int t0 = blockIdx.y * 128;
    // softmax params for the row this thread loads (fixed across loop)
    float m_r   = g_mrow[(size_t)z*TT + t0 + aRow];
    float li_r  = g_linv[(size_t)z*TT + t0 + aRow];
    float acc[8][8] = {};
    for (int s0 = 0; s0 < TT; s0 += 16) {
        float4 p0 = *(const float4*)(S + (size_t)(t0 + aRow)*TT + s0 + aColB);
        float4 p1 = *(const float4*)(S + (size_t)(t0 + aRow)*TT + s0 + aColB + 4);
        As[aColB+0][aRow] = __expf(p0.x - m_r) * li_r;
        As[aColB+1][aRow] = __expf(p0.y - m_r) * li_r;
        As[aColB+2][aRow] = __expf(p0.z - m_r) * li_r;
        As[aColB+3][aRow] = __expf(p0.w - m_r) * li_r;
        As[aColB+4][aRow] = __expf(p1.x - m_r) * li_r;
        As[aColB+5][aRow] = __expf(p1.y - m_r) * li_r;
        As[aColB+6][aRow] = __expf(p1.z - m_r) * li_r;
        As[aColB+7][aRow] = __expf(p1.w - m_r) * li_r;
        *(float4*)&Bs[bRow][bColB]   = *(const float4*)(V + (size_t)(s0 + bRow)*DMODEL + d0 + bColB);
        *(float4*)&Bs[bRow][bColB+4] = *(const float4*)(V + (size_t)(s0 + bRow)*DMODEL + d0 + bColB + 4);
        __syncthreads();
        #pragma unroll
        for (int kk = 0; kk < 16; kk++) {
            float4 a0 = *(const float4*)&As[kk][ty*8];
            float4 a1 = *(const float4*)&As[kk][ty*8+4];
            float4 b0 = *(const float4*)&Bs[kk][tx*8];
            float4 b1 = *(const float4*)&Bs[kk][tx*8+4];
            float ar[8] = {a0.x,a0.y,a0.z,a0.w,a1.x,a1.y,a1.z,a1.w};
            float br[8] = {b0.x,b0.y,b0.z,b0.w,b1.x,b1.y,b1.z,b1.w};
            #pragma unroll
            for (int i = 0; i < 8; i++)
                #pragma unroll
                for (int j = 0; j < 8; j++) acc[i][j] += ar[i]*br[j];
        }
        __syncthreads();
    }
    float mk[8];
    int din[8];
    #pragma unroll
    for (int j = 0; j < 8; j++) {
        int d = d0 + tx*8 + j;
        mk[j]  = msk[d];
        din[j] = (d >= dlo) && (d < dhi);
    }
    #pragma unroll
    for (int i = 0; i < 8; i++) {
        int t = t0 + ty*8 + i;
        #pragma unroll
        for (int j = 0; j < 8; j++) {
            if (din[j]) {
                int d = d0 + tx*8 + j;
                atomicAdd(&g_ctx[(size_t)b*TT*DMODEL + (size_t)t*DMODEL + d], acc[i][j] * mk[j]);
            }
        }
    }
}

// ---------------- K6: out = ctx @ Wout + bout + query -> g_res ----------------
__global__ __launch_bounds__(256) void sgemm_out(const float* __restrict__ B,
                                                 const float* __restrict__ bias,
                                                 const float* __restrict__ resid) {
    const int K = DMODEL, N = DMODEL;
    __shared__ float As[16][128];
    __shared__ float Bs[16][128];
    int tid = threadIdx.x;
    int tx = tid & 15, ty = tid >> 4;
    int aRow = tid >> 1, aColB = (tid & 1) << 3;
    int bRow = tid >> 4, bColB = (tid & 15) << 3;
    const float* Ablk = g_ctx + (size_t)(blockIdx.y * 128) * K;
    const float* Bblk = B + blockIdx.x * 128;
    float acc[8][8] = {};
    for (int k0 = 0; k0 < K; k0 += 16) {
        float4 a0v = *(const float4*)(Ablk + (size_t)aRow * K + k0 + aColB);
        float4 a1v = *(const float4*)(Ablk + (size_t)aRow * K + k0 + aColB + 4);
        As[aColB+0][aRow] = a0v.x; As[aColB+1][aRow] = a0v.y;
        As[aColB+2][aRow] = a0v.z; As[aColB+3][aRow] = a0v.w;
        As[aColB+4][aRow] = a1v.x; As[aColB+5][aRow] = a1v.y;
        As[aColB+6][aRow] = a1v.z; As[aColB+7][aRow] = a1v.w;
        *(float4*)&Bs[bRow][bColB]   = *(const float4*)(Bblk + (size_t)(k0 + bRow) * N + bColB);
        *(float4*)&Bs[bRow][bColB+4] = *(const float4*)(Bblk + (size_t)(k0 + bRow) * N + bColB + 4);
        __syncthreads();
        #pragma unroll
        for (int kk = 0; kk < 16; kk++) {
            float4 a0 = *(const float4*)&As[kk][ty*8];
            float4 a1 = *(const float4*)&As[kk][ty*8+4];
            float4 b0 = *(const float4*)&Bs[kk][tx*8];
            float4 b1 = *(const float4*)&Bs[kk][tx*8+4];
            float ar[8] = {a0.x,a0.y,a0.z,a0.w,a1.x,a1.y,a1.z,a1.w};
            float br[8] = {b0.x,b0.y,b0.z,b0.w,b1.x,b1.y,b1.z,b1.w};
            #pragma unroll
            for (int i = 0; i < 8; i++)
                #pragma unroll
                for (int j = 0; j < 8; j++) acc[i][j] += ar[i]*br[j];
        }
        __syncthreads();
    }
    int row0 = blockIdx.y*128 + ty*8;
    int col0 = blockIdx.x*128 + tx*8;
    #pragma unroll
    for (int i = 0; i < 8; i++) {
        int row = row0 + i;
        #pragma unroll
        for (int j = 0; j < 8; j++) {
            int col = col0 + j;
            g_res[(size_t)row*DMODEL + col] =
                acc[i][j] + bias[col] + resid[(size_t)row*DMODEL + col];
        }
    }
}

// ---------------- K7: LayerNorm -> d_out ----------------
__global__ __launch_bounds__(256) void ln_kernel(const float* __restrict__ gamma,
                                                 const float* __restrict__ beta,
                                                 float* __restrict__ out) {
    int row = blockIdx.x;
    int tid = threadIdx.x;
    float2 v = ((const float2*)(g_res + (size_t)row*DMODEL))[tid];
    float s = block_reduce_sum(v.x + v.y);
    float mu = s * (1.0f / DMODEL);
    float d0 = v.x - mu, d1 = v.y - mu;
    float sq = block_reduce_sum(d0*d0 + d1*d1);
    float var = sq * (1.0f / DMODEL);
    float r = rsqrtf(var + 1e-5f);
    float2 g  = ((const float2*)gamma)[tid];
    float2 bt = ((const float2*)beta)[tid];
    float2 o;
    o.x = d0 * r * g.x + bt.x;
    o.y = d1 * r * g.y + bt.y;
    ((float2*)(out + (size_t)row*DMODEL))[tid] = o;
}

// ---------------- launch ----------------
extern "C" void kernel_launch(void* const* d_in, const int* in_sizes, int n_in,
                              void* d_out, int out_size) {
    const float* query = (const float*)d_in[0];
    const float* hw    = (const float*)d_in[1];
    const float* Wqkv  = (const float*)d_in[2];
    const float* bqkv  = (const float*)d_in[3];
    const float* Wout  = (const float*)d_in[4];
    const float* bout  = (const float*)d_in[5];
    const float* gamma = (const float*)d_in[6];
    const float* beta  = (const float*)d_in[7];
    const unsigned char* kpm = (const unsigned char*)d_in[8];
    float* out = (float*)d_out;

    head_params_kernel<<<1, DMODEL>>>(hw);
    sgemm_qkv<<<dim3(3*DMODEL/128, BB*TT/128), 256>>>(query, Wqkv, bqkv);
    zero_ctx_kernel<<<(BB*TT*DMODEL/4)/256, 256>>>();
    scores_kernel<<<dim3(TT/128, TT/128, HH*BB), 256>>>(kpm);
    combine_kernel<<<NROWS/256, 256>>>();
    ctx_kernel<<<dim3(DMODEL/128, TT/128, HH*BB), 256>>>();
    sgemm_out<<<dim3(DMODEL/128, BB*TT/128), 256>>>(Wout, bout, query);
    ln_kernel<<<BB*TT, 256>>>(gamma, beta, out);
}